// round 10
// baseline (speedup 1.0000x reference)
#include <cuda_runtime.h>
#include <math.h>

#define CHN   64        // B*C
#define DD    96        // depth slices per channel
#define HWN   16384     // 128*128
#define SPC   8         // slices per CTA
#define CPC   12        // CTAs per channel
#define NCTA  768       // 64 * 12  (6 CTAs/SM max -> single wave, 42 regs/thread)
#define NTHR  256

__device__ double g_acc[CHN][4];      // [mass, wx, wy, wz]
__device__ unsigned int g_cnt = 0;

__constant__ float EXP_POS[32][3] = {
    {0.00000000f,-0.60000000f,0.7f},{0.12474701f,-0.58688856f,0.7f},
    {0.24404199f,-0.54812727f,0.7f},{0.35267115f,-0.48541020f,0.7f},
    {0.44588690f,-0.40147836f,0.7f},{0.51961524f,-0.30000000f,0.7f},
    {0.57063391f,-0.18541020f,0.7f},{0.59671314f,-0.06271708f,0.7f},
    {0.59671314f, 0.06271708f,0.7f},{0.57063391f, 0.18541020f,0.7f},
    {0.51961524f, 0.30000000f,0.7f},{0.44588690f, 0.40147836f,0.7f},
    {0.35267115f, 0.48541020f,0.7f},{0.24404199f, 0.54812727f,0.7f},
    {0.12474701f, 0.58688856f,0.7f},{0.00000000f, 0.60000000f,0.7f},
    {0.00000000f, 0.55000000f,0.3f},{0.11435143f, 0.53798118f,0.3f},
    {0.22370515f, 0.50245000f,0.3f},{0.32328189f, 0.44495935f,0.3f},
    {0.40872965f, 0.36802183f,0.3f},{0.47631397f, 0.27500000f,0.3f},
    {0.52308108f, 0.16995935f,0.3f},{0.54698704f, 0.05749065f,0.3f},
    {0.54698704f,-0.05749065f,0.3f},{0.52308108f,-0.16995935f,0.3f},
    {0.47631397f,-0.27500000f,0.3f},{0.40872965f,-0.36802183f,0.3f},
    {0.32328189f,-0.44495935f,0.3f},{0.22370515f,-0.50245000f,0.3f},
    {0.11435143f,-0.53798118f,0.3f},{0.00000000f,-0.55000000f,0.3f}};

__constant__ int ADJ_F[28] = {0,1,2,3,4,5,6, 8,9,10,11,12,13,14,
                              16,17,18,19,20,21,22, 24,25,26,27,28,29,30};
__constant__ int OPP1[16] = {0,1,2,3,4,5,6,7, 16,17,18,19,20,21,22,23};
__constant__ int OPP2[16] = {15,14,13,12,11,10,9,8, 31,30,29,28,27,26,25,24};
__constant__ int GIDX[4][12] = {
    {6,7,8,9,22,23,24,25, 0,0,0,0},
    {5,10,21,26, 0,0,0,0,0,0,0,0},
    {3,4,11,12,19,20,27,28, 0,0,0,0},
    {0,1,2,13,14,15,16,17,18,29,30,31}};
__constant__ int GN[4] = {8, 4, 8, 12};
__constant__ double GINVN[4]  = {1.0/8.0, 1.0/4.0, 1.0/8.0, 1.0/12.0};
__constant__ double GINVN1[4] = {1.0/7.0, 1.0/3.0, 1.0/7.0, 1.0/11.0};

__global__ __launch_bounds__(NTHR, 6) void tooth_loss_kernel(const float* __restrict__ seg,
                                                             float* __restrict__ out) {
    const int tid = threadIdx.x;
    const int bc   = blockIdx.x / CPC;           // channel 0..63
    const int grp  = blockIdx.x - bc * CPC;      // 0..11 within channel
    const int d0   = grp * SPC;

    const float4* __restrict__ p =
        (const float4*)(seg + (size_t)(bc * DD + d0) * HWN) + tid;

    // Per-thread separable weights:
    //   elem linear idx = 4*(tid + 256k), col = (4*tid)&127, row = (tid>>5)+8k
    const float w0 = (float)((4 * tid) & 127);
    const float h0 = (float)(tid >> 5);

    float m = 0.f, u = 0.f, ts = 0.f, wzd = 0.f;
#pragma unroll
    for (int s = 0; s < SPC; s++) {
        float4 ma = make_float4(0.f, 0.f, 0.f, 0.f);   // plain component sums
        float4 ra = make_float4(0.f, 0.f, 0.f, 0.f);   // k-weighted component sums
#pragma unroll
        for (int k = 0; k < 16; k++) {
            float4 v = __ldcs(&p[s * 4096 + k * 256]);
            float fk = (float)k;
            ma.x += v.x;                ma.y += v.y;
            ma.z += v.z;                ma.w += v.w;
            ra.x = fmaf(fk, v.x, ra.x); ra.y = fmaf(fk, v.y, ra.y);
            ra.z = fmaf(fk, v.z, ra.z); ra.w = fmaf(fk, v.w, ra.w);
        }
        float ms  = (ma.x + ma.y) + (ma.z + ma.w);
        float us  = (ra.x + ra.y) + (ra.z + ra.w);
        float tss = fmaf(3.f, ma.w, fmaf(2.f, ma.z, ma.y));
        m  += ms;
        u  += us;
        ts += tss;
        wzd = fmaf((float)(d0 + s), ms, wzd);
    }
    float wx = fmaf(w0, m, ts);
    float wy = fmaf(h0, m, 8.f * u);

    for (int o = 16; o; o >>= 1) {
        m   += __shfl_down_sync(0xffffffffu, m,   o);
        wx  += __shfl_down_sync(0xffffffffu, wx,  o);
        wy  += __shfl_down_sync(0xffffffffu, wy,  o);
        wzd += __shfl_down_sync(0xffffffffu, wzd, o);
    }
    __shared__ float sm[4][8];
    __shared__ bool s_last;
    int lane = tid & 31, warp = tid >> 5;
    if (lane == 0) { sm[0][warp] = m; sm[1][warp] = wx; sm[2][warp] = wy; sm[3][warp] = wzd; }
    if (tid == 0) s_last = false;
    __syncthreads();
    if (warp == 0) {
        m   = (lane < 8) ? sm[0][lane] : 0.f;
        wx  = (lane < 8) ? sm[1][lane] : 0.f;
        wy  = (lane < 8) ? sm[2][lane] : 0.f;
        wzd = (lane < 8) ? sm[3][lane] : 0.f;
        for (int o = 4; o; o >>= 1) {
            m   += __shfl_down_sync(0xffffffffu, m,   o);
            wx  += __shfl_down_sync(0xffffffffu, wx,  o);
            wy  += __shfl_down_sync(0xffffffffu, wy,  o);
            wzd += __shfl_down_sync(0xffffffffu, wzd, o);
        }
        if (lane == 0) {
            atomicAdd(&g_acc[bc][0], (double)m);
            atomicAdd(&g_acc[bc][1], (double)wx);
            atomicAdd(&g_acc[bc][2], (double)wy);
            atomicAdd(&g_acc[bc][3], (double)wzd);
            __threadfence();
            unsigned int old = atomicAdd(&g_cnt, 1u);
            if (old == NCTA - 1) s_last = true;
        }
    }
    __syncthreads();
    if (!s_last) return;

    // ================= last block: finalize =================
    __threadfence();

    __shared__ float  sctr[CHN][3];
    __shared__ double svol[CHN];
    __shared__ float  wpart[3][8];
    __shared__ double an8[8];

    if (tid < CHN) {
        double mm = g_acc[tid][0];
        double ax = g_acc[tid][1];
        double ay = g_acc[tid][2];
        double az = g_acc[tid][3];
        svol[tid] = mm;
        double inv = (mm > 0.0) ? (1.0 / mm) : 0.0;
        sctr[tid][0] = (float)(ax * inv * (1.0 / 128.0));
        sctr[tid][1] = (float)(ay * inv * (1.0 / 128.0));
        sctr[tid][2] = (float)(az * inv * (1.0 /  96.0));
    }
    __syncthreads();

    // reset for next graph replay (after all reads)
    if (tid < CHN * 4) ((double*)g_acc)[tid] = 0.0;
    if (tid == 0) g_cnt = 0;

    float lm = 0.f, sp = 0.f, sy = 0.f;

    if (tid < 64) {
        int c = tid & 31;
        const float* A = sctr[tid];
        float dx = A[0] - EXP_POS[c][0];
        float dy = A[1] - EXP_POS[c][1];
        float dz = A[2] - EXP_POS[c][2];
        lm = dx * dx + dy * dy + dz * dz;
    } else if (tid < 120) {
        int k = tid - 64, pr = k >> 1, b = k & 1;
        int i = ADJ_F[pr], j = i + 1;
        const float* A = sctr[b * 32 + i];
        const float* B = sctr[b * 32 + j];
        float dx = A[0] - B[0], dy = A[1] - B[1], dz = A[2] - B[2];
        float r = sqrtf(dx * dx + dy * dy + dz * dz) - 0.1f;
        if (r > 0.f) sp = r * 0.5f;
    } else if (tid < 152) {
        int k = tid - 120, pr = k >> 1, b = k & 1;
        const float* A = sctr[b * 32 + OPP1[pr]];
        const float* B = sctr[b * 32 + OPP2[pr]];
        float dx = A[0] - B[0], dy = A[1] - B[1], dz = A[2] - B[2];
        sp = (dx * dx + dy * dy) * 0.25f;
        float r = 0.3f - fabsf(dz);
        if (r > 0.f) sp += r * 0.5f;
    } else if (tid < 184) {
        int k = tid - 152, pr = k >> 1, b = k & 1;
        const float* A = sctr[b * 32 + OPP1[pr]];
        const float* B = sctr[b * 32 + OPP2[pr]];
        float dy = A[1] - B[1], dz = A[2] - B[2];
        float sx = A[0] + B[0];
        sy = (dy * dy + dz * dz) * 0.25f + sx * sx * 0.5f;
    } else if (tid < 192) {
        int k = tid - 184, g = k >> 1, b = k & 1;
        int n = GN[g];
        double mean = 0.0;
        for (int i = 0; i < n; i++) mean += svol[b * 32 + GIDX[g][i]];
        mean *= GINVN[g];
        double ss = 0.0;
        for (int i = 0; i < n; i++) {
            double dv = svol[b * 32 + GIDX[g][i]] - mean;
            ss += dv * dv;
        }
        an8[k] = ss * GINVN1[g] * 0.5;
    }

    for (int o = 16; o; o >>= 1) {
        lm += __shfl_down_sync(0xffffffffu, lm, o);
        sp += __shfl_down_sync(0xffffffffu, sp, o);
        sy += __shfl_down_sync(0xffffffffu, sy, o);
    }
    if (lane == 0) { wpart[0][warp] = lm; wpart[1][warp] = sp; wpart[2][warp] = sy; }
    __syncthreads();

    if (tid == 0) {
        float L = 0.f, S = 0.f, Y = 0.f;
        for (int w = 0; w < 8; w++) { L += wpart[0][w]; S += wpart[1][w]; Y += wpart[2][w]; }
        double A = 0.0;
        for (int k = 0; k < 8; k++) A += an8[k];

        double Ld = (double)(L * (1.f / 192.f)) * 10.0;
        double Sd = (double)S * 5.0;
        double Yd = (double)Y * 3.0;
        double Ad = A * 7.0;
        double total = Ld + Sd + Yd + Ad;

        out[0] = (float)Ld;
        out[1] = (float)Sd;
        out[2] = (float)Yd;
        out[3] = (float)Ad;
        out[4] = (float)total;
    }
}

extern "C" void kernel_launch(void* const* d_in, const int* in_sizes, int n_in,
                              void* d_out, int out_size) {
    const float* seg = (const float*)d_in[0];
    float* out = (float*)d_out;
    (void)in_sizes; (void)n_in; (void)out_size;

    tooth_loss_kernel<<<NCTA, NTHR>>>(seg, out);
}